// round 16
// baseline (speedup 1.0000x reference)
#include <cuda_runtime.h>
#include <cstdint>

// Geometric product in Cl(3,0,1): out[n,k] = sum_{i,j} a[n,i] b[n,j] C[i,j,k]
// Structure constants baked in at compile time (metric = 1,1,1,0).
//
// R16 = R11/R14 (best, reproduced: cp.async.cg staged inputs with L2
// evict-first, XOR-swizzled conflict-free smem, constant-folded 192-FFMA
// product, smem-gathered unit-stride __stcs stores) with one knob:
// __launch_bounds__(256, 5) caps registers at 48 (was 59) -> 5 CTAs/SM
// (40 warps vs 32). Occupancy was register-bound; everything else is at
// the measured ~6.2 TB/s mixed-stream ceiling.

static __host__ __device__ constexpr int cayley_sign(int A, int B) {
    if (A & B & 8) return 0;            // degenerate generator e3 (metric 0)
    int s = 0;
    int sa = A >> 1;
    while (sa) {
        int x = sa & B;
        while (x) { s += 1; x &= (x - 1); }
        sa >>= 1;
    }
    return (s & 1) ? -1 : 1;
}

// Swizzled position for flat float4 index idx within a 1024-float4 tile:
//   r = idx>>2 (row), c = idx&3 (quad); pos = 4r | (c ^ ((r>>1)&3))
// Conflict-free for both unit-stride staging and per-row access.
static __device__ __forceinline__ int swz(int idx) {
    const int r = idx >> 2;
    const int c = idx & 3;
    return (r << 2) | (c ^ ((r >> 1) & 3));
}

static __device__ __forceinline__ uint32_t smem_u32(const void* p) {
    return (uint32_t)__cvta_generic_to_shared(p);
}

static __device__ __forceinline__ uint64_t evict_first_policy() {
    uint64_t pol;
    asm("createpolicy.fractional.L2::evict_first.b64 %0, 1.0;" : "=l"(pol));
    return pol;
}

static __device__ __forceinline__ void cp_async16_ef(uint32_t dst, const void* src,
                                                     uint64_t pol) {
    asm volatile("cp.async.cg.shared.global.L2::cache_hint [%0], [%1], 16, %2;"
                 :: "r"(dst), "l"(src), "l"(pol) : "memory");
}

__global__ void __launch_bounds__(256, 5)
gp_kernel(const float4* __restrict__ a4,
          const float4* __restrict__ b4,
          float4* __restrict__ o4,
          int n_rows) {
    __shared__ __align__(16) float4 sa[1024];   // 16 KB, reused for output
    __shared__ __align__(16) float4 sb[1024];   // 16 KB

    const int t     = threadIdx.x;
    const int base4 = blockIdx.x * 1024;
    const int row0  = blockIdx.x * 256;
    const bool full_tile = (row0 + 256 <= n_rows);
    const uint64_t pol = evict_first_policy();

    // ---- Stage a and b: cp.async (L2 evict-first) gmem -> swizzled smem ----
    if (full_tile) {
        #pragma unroll
        for (int v = 0; v < 4; ++v) {
            const int idx = v * 256 + t;
            cp_async16_ef(smem_u32(&sa[swz(idx)]), &a4[base4 + idx], pol);
            cp_async16_ef(smem_u32(&sb[swz(idx)]), &b4[base4 + idx], pol);
        }
    } else {
        #pragma unroll
        for (int v = 0; v < 4; ++v) {
            const int idx = v * 256 + t;
            const int pos = swz(idx);
            if ((base4 + idx) < n_rows * 4) {
                cp_async16_ef(smem_u32(&sa[pos]), &a4[base4 + idx], pol);
                cp_async16_ef(smem_u32(&sb[pos]), &b4[base4 + idx], pol);
            } else {
                sa[pos] = make_float4(0.f, 0.f, 0.f, 0.f);
                sb[pos] = make_float4(0.f, 0.f, 0.f, 0.f);
            }
        }
    }
    asm volatile("cp.async.commit_group;" ::: "memory");
    asm volatile("cp.async.wait_group 0;" ::: "memory");
    __syncthreads();

    // ---- Each thread reads its own row (conflict-free via swizzle) ----
    float a[16], b[16];
    const int s = (t >> 1) & 3;
    #pragma unroll
    for (int v = 0; v < 4; ++v) {
        const int u = v ^ s;                       // physical quad holding logical quad v
        const float4 va = sa[(t << 2) | u];
        const float4 vb = sb[(t << 2) | u];
        a[v * 4 + 0] = va.x; a[v * 4 + 1] = va.y;
        a[v * 4 + 2] = va.z; a[v * 4 + 3] = va.w;
        b[v * 4 + 0] = vb.x; b[v * 4 + 1] = vb.y;
        b[v * 4 + 2] = vb.z; b[v * 4 + 3] = vb.w;
    }

    // ---- 192 straight-line FFMAs ----
    float c[16];
    #pragma unroll
    for (int k = 0; k < 16; ++k) c[k] = 0.0f;

    #pragma unroll
    for (int A = 0; A < 16; ++A) {
        #pragma unroll
        for (int B = 0; B < 16; ++B) {
            const int sg = cayley_sign(A, B);
            if (sg == 1) {
                c[A ^ B] = fmaf(a[A], b[B], c[A ^ B]);
            } else if (sg == -1) {
                c[A ^ B] = fmaf(-a[A], b[B], c[A ^ B]);
            }
        }
    }

    // ---- Write own output row into sa (own region; no pre-sync needed) ----
    #pragma unroll
    for (int v = 0; v < 4; ++v) {
        const int u = v ^ s;
        sa[(t << 2) | u] = make_float4(c[v * 4 + 0], c[v * 4 + 1],
                                       c[v * 4 + 2], c[v * 4 + 3]);
    }
    __syncthreads();

    // ---- Gather + unit-stride streaming global stores (evict-first) ----
    if (full_tile) {
        #pragma unroll
        for (int v = 0; v < 4; ++v) {
            const int idx = v * 256 + t;
            __stcs(&o4[base4 + idx], sa[swz(idx)]);
        }
    } else {
        #pragma unroll
        for (int v = 0; v < 4; ++v) {
            const int idx = v * 256 + t;
            if ((base4 + idx) < n_rows * 4)
                __stcs(&o4[base4 + idx], sa[swz(idx)]);
        }
    }
}

extern "C" void kernel_launch(void* const* d_in, const int* in_sizes, int n_in,
                              void* d_out, int out_size) {
    const float4* a4 = (const float4*)d_in[0];
    const float4* b4 = (const float4*)d_in[1];
    // d_in[2] is the Cayley tensor; values are baked in at compile time.
    float4* o4 = (float4*)d_out;

    const int n_rows = in_sizes[0] / 16;
    const int blocks = (n_rows + 255) / 256;
    gp_kernel<<<blocks, 256>>>(a4, b4, o4, n_rows);
}